// round 4
// baseline (speedup 1.0000x reference)
#include <cuda_runtime.h>
#include <math_constants.h>

#define DIM 128
#define KCODES 2048
#define NROWS 65536
#define NZ (NROWS * DIM)
#define TILE_M 64
#define TILE_N 64
#define NTHREADS 128
#define NCHUNKS (KCODES / TILE_N)

__device__ __align__(16) float g_t[KCODES];     // ||e_j||^2
__device__ int   g_idx[NROWS];
__device__ float g_part[1024];

// ---- f32x2 helpers ----
#define FMA2(d, a, b) asm("fma.rn.f32x2 %0, %1, %2, %0;" : "+l"(d) : "l"(a), "l"(b))

static __device__ __forceinline__ unsigned long long pack2(float x) {
    unsigned long long r;
    unsigned int u = __float_as_uint(x);
    asm("mov.b64 %0, {%1, %1};" : "=l"(r) : "r"(u));
    return r;
}
static __device__ __forceinline__ void unpack2(unsigned long long v, float& lo, float& hi) {
    unsigned int a, b;
    asm("mov.b64 {%0, %1}, %2;" : "=r"(a), "=r"(b) : "l"(v));
    lo = __uint_as_float(a);
    hi = __uint_as_float(b);
}

// ---- ||e_j||^2 ----
__global__ void k_embnorm(const float* __restrict__ emb) {
    int j = blockIdx.x * blockDim.x + threadIdx.x;
    if (j < KCODES) {
        const float* e = emb + (size_t)j * DIM;
        float s = 0.f;
        #pragma unroll 8
        for (int k = 0; k < DIM; ++k)
            s = __fadd_rn(s, __fmul_rn(e[k], e[k]));
        g_t[j] = s;
    }
}

// ---- fused distance-GEMM + argmin ----
// Block: 64 rows x 2048 codes (32 chunks of 64). 128 threads: thread tile 4 rows x 8 codes.
// f32x2 packs ROW PAIRS: z operand = natural LDS.128 of k-major zs (no MOVs).
// e operand = per-code duplicated pair, built once per chunk in smem (amortized MOVs),
// stored j-interleaved + k-XOR swizzled so mainloop LDS.128 are conflict-free.
__global__ __launch_bounds__(NTHREADS, 2)
void k_argmin(const float* __restrict__ z, const float* __restrict__ emb) {
    extern __shared__ char smc[];
    float* zs  = (float*)smc;                       // [128k][64r] z, k-major      (32 KB)
    char*  es2 = smc + DIM * TILE_M * 4;            // [128k][512B] dup-e chunk    (64 KB)
    float* tall = (float*)(es2 + DIM * 512);        // [2048] ||e||^2              (8 KB)
    float* ss   = tall + KCODES;                    // [64]   ||z||^2 per row

    const int tid = threadIdx.x;
    const int rbase = blockIdx.x * TILE_M;

    // stage full ||e||^2 table once
    for (int i = tid; i < KCODES / 4; i += NTHREADS)
        ((float4*)tall)[i] = ((const float4*)g_t)[i];

    // load z tile (transpose to k-major); conflict-free STS (bank = r mod 32)
    for (int i = tid; i < TILE_M * (DIM / 4); i += NTHREADS) {
        int r  = i & (TILE_M - 1);
        int k4 = i >> 6;
        float4 v = *(const float4*)(z + (size_t)(rbase + r) * DIM + k4 * 4);
        zs[(k4 * 4 + 0) * TILE_M + r] = v.x;
        zs[(k4 * 4 + 1) * TILE_M + r] = v.y;
        zs[(k4 * 4 + 2) * TILE_M + r] = v.z;
        zs[(k4 * 4 + 3) * TILE_M + r] = v.w;
    }
    __syncthreads();

    // row norms (fp32 sequential k)
    if (tid < TILE_M) {
        float s = 0.f;
        #pragma unroll 8
        for (int k = 0; k < DIM; ++k) {
            float v = zs[k * TILE_M + tid];
            s = __fadd_rn(s, __fmul_rn(v, v));
        }
        ss[tid] = s;
    }
    __syncthreads();

    const int tc = tid & 7;    // code group: codes tc*8 .. tc*8+7 of the chunk
    const int tr = tid >> 3;   // row group:  rows 4tr .. 4tr+3

    float s_r[4];
    #pragma unroll
    for (int r = 0; r < 4; ++r) s_r[r] = ss[tr * 4 + r];

    float best[4];
    int   bidx[4];
    #pragma unroll
    for (int r = 0; r < 4; ++r) { best[r] = CUDART_INF_F; bidx[r] = 0; }

    for (int ch = 0; ch < NCHUNKS; ++ch) {
        const int cbase = ch * TILE_N;
        __syncthreads();  // previous chunk's es2 fully consumed

        // build dup-e chunk: code cl, dims k4*4..k4*4+3.
        // dup pair for code cl at k lives at: k*512 + jj*128 + ((tcg ^ ((k>>2)&7))<<4) + b*8
        //   jj = (cl&7)>>1, tcg = cl>>3, b = cl&1
        for (int i = tid; i < TILE_N * (DIM / 4); i += NTHREADS) {
            int cl = i >> 5;
            int k4 = i & 31;
            float4 v = *(const float4*)(emb + (size_t)(cbase + cl) * DIM + k4 * 4);
            int jj  = (cl & 7) >> 1;
            int tcg = cl >> 3;
            int b   = cl & 1;
            char* base = es2 + jj * 128 + b * 8;
            #pragma unroll
            for (int kk = 0; kk < 4; ++kk) {
                int k = k4 * 4 + kk;
                *(unsigned long long*)(base + k * 512 + ((tcg ^ (k4 & 7)) << 4)) =
                    pack2(((const float*)&v)[kk]);
            }
        }
        __syncthreads();

        unsigned long long acc[16];   // acc[rp*8 + c]: rp = row pair (0,1), c = code 0..7
        #pragma unroll
        for (int i = 0; i < 16; ++i) acc[i] = 0ull;

        #pragma unroll 4
        for (int k = 0; k < DIM; ++k) {
            const char* ekb = es2 + k * 512 + ((tc ^ ((k >> 2) & 7)) << 4);
            ulonglong2 e0 = *(const ulonglong2*)(ekb);         // codes 0,1 (dup pairs)
            ulonglong2 e1 = *(const ulonglong2*)(ekb + 128);   // codes 2,3
            ulonglong2 e2 = *(const ulonglong2*)(ekb + 256);   // codes 4,5
            ulonglong2 e3 = *(const ulonglong2*)(ekb + 384);   // codes 6,7
            ulonglong2 zp = *(const ulonglong2*)(zs + k * TILE_M + tr * 4);
            // zp.x = rows (4tr,4tr+1), zp.y = rows (4tr+2,4tr+3)
            FMA2(acc[0], zp.x, e0.x); FMA2(acc[1], zp.x, e0.y);
            FMA2(acc[2], zp.x, e1.x); FMA2(acc[3], zp.x, e1.y);
            FMA2(acc[4], zp.x, e2.x); FMA2(acc[5], zp.x, e2.y);
            FMA2(acc[6], zp.x, e3.x); FMA2(acc[7], zp.x, e3.y);
            FMA2(acc[8],  zp.y, e0.x); FMA2(acc[9],  zp.y, e0.y);
            FMA2(acc[10], zp.y, e1.x); FMA2(acc[11], zp.y, e1.y);
            FMA2(acc[12], zp.y, e2.x); FMA2(acc[13], zp.y, e2.y);
            FMA2(acc[14], zp.y, e3.x); FMA2(acc[15], zp.y, e3.y);
        }

        // dist = fl(fl(s - 2m) + t), identical rounding chain to reference.
        // per row, codes ascending (c = 0..7) -> correct lowest-index tie-break.
        #pragma unroll
        for (int rp = 0; rp < 2; ++rp) {
            #pragma unroll
            for (int c = 0; c < 8; ++c) {
                float mlo, mhi;
                unpack2(acc[rp * 8 + c], mlo, mhi);
                int code = cbase + tc * 8 + c;
                float t = tall[code];
                int r0 = rp * 2;      // rows 4tr + r0, 4tr + r0 + 1
                float d0 = __fadd_rn(__fsub_rn(s_r[r0],     __fmul_rn(2.f, mlo)), t);
                float d1 = __fadd_rn(__fsub_rn(s_r[r0 + 1], __fmul_rn(2.f, mhi)), t);
                if (d0 < best[r0])     { best[r0] = d0;     bidx[r0] = code; }
                if (d1 < best[r0 + 1]) { best[r0 + 1] = d1; bidx[r0 + 1] = code; }
            }
        }
    }

    // cross-thread (8-lane tc group) reduction, tie -> lowest index
    #pragma unroll
    for (int r = 0; r < 4; ++r) {
        float v = best[r];
        int   ix = bidx[r];
        #pragma unroll
        for (int off = 4; off > 0; off >>= 1) {
            float v2 = __shfl_down_sync(0xffffffffu, v, off, 8);
            int   i2 = __shfl_down_sync(0xffffffffu, ix, off, 8);
            if (v2 < v || (v2 == v && i2 < ix)) { v = v2; ix = i2; }
        }
        if (tc == 0) g_idx[rbase + tr * 4 + r] = ix;
    }
}

// ---- gather + straight-through + indices + loss partials ----
__global__ __launch_bounds__(256)
void k_out(const float* __restrict__ z, const float* __restrict__ emb,
           float* __restrict__ out, long long out_size) {
    __shared__ float red[256];
    const int tid = threadIdx.x;
    const long long row0 = (long long)blockIdx.x * 64;
    float lsum = 0.f;

    for (int i = tid; i < 64 * (DIM / 4); i += 256) {
        long long r  = row0 + (i >> 5);
        int       d4 = (i & 31) * 4;
        int idx = g_idx[r];
        float4 q  = *(const float4*)(emb + (size_t)idx * DIM + d4);
        long long gi = r * DIM + d4;
        float4 zz = *(const float4*)(z + gi);
        float4 o; float df;
        df = __fsub_rn(q.x, zz.x); o.x = __fadd_rn(zz.x, df); lsum += df * df;
        df = __fsub_rn(q.y, zz.y); o.y = __fadd_rn(zz.y, df); lsum += df * df;
        df = __fsub_rn(q.z, zz.z); o.z = __fadd_rn(zz.z, df); lsum += df * df;
        df = __fsub_rn(q.w, zz.w); o.w = __fadd_rn(zz.w, df); lsum += df * df;
        if (gi + 3 < out_size) *(float4*)(out + gi) = o;
    }

    if (tid < 64) {
        long long r  = row0 + tid;
        long long gi = (long long)NZ + r;
        if (gi < out_size) out[gi] = (float)g_idx[r];
    }

    red[tid] = lsum;
    __syncthreads();
    for (int s = 128; s > 0; s >>= 1) {
        if (tid < s) red[tid] += red[tid + s];
        __syncthreads();
    }
    if (tid == 0) g_part[blockIdx.x] = red[0];
}

// ---- deterministic final loss reduce ----
__global__ void k_final(float* __restrict__ out, long long out_size) {
    __shared__ float red[256];
    const int tid = threadIdx.x;
    float s = 0.f;
    for (int i = tid; i < 1024; i += 256) s += g_part[i];
    red[tid] = s;
    __syncthreads();
    for (int w = 128; w > 0; w >>= 1) {
        if (tid < w) red[tid] += red[tid + w];
        __syncthreads();
    }
    if (tid == 0) {
        float m = red[0] / (float)NZ;
        float loss = __fadd_rn(m, __fmul_rn(0.25f, m));
        long long li = (long long)NZ + NROWS;
        if (li < out_size) out[li] = loss;
    }
}

extern "C" void kernel_launch(void* const* d_in, const int* in_sizes, int n_in,
                              void* d_out, int out_size) {
    const float* z   = (const float*)d_in[0];
    const float* emb = (const float*)d_in[1];
    float* out = (float*)d_out;

    const int smem_bytes = DIM * TILE_M * 4        // zs
                         + DIM * 512               // es2 (dup-e chunk, 64 codes)
                         + KCODES * 4              // tall
                         + TILE_M * 4;             // ss
    cudaFuncSetAttribute(k_argmin, cudaFuncAttributeMaxDynamicSharedMemorySize, smem_bytes);

    k_embnorm<<<(KCODES + 255) / 256, 256>>>(emb);
    k_argmin<<<NROWS / TILE_M, NTHREADS, smem_bytes>>>(z, emb);
    k_out<<<NROWS / 64, 256>>>(z, emb, out, (long long)out_size);
    k_final<<<1, 256>>>(out, (long long)out_size);
}

// round 8
// speedup vs baseline: 1.9351x; 1.9351x over previous
#include <cuda_runtime.h>
#include <cuda_fp16.h>
#include <math_constants.h>
#include <cstdint>

#define DIM 128
#define KCODES 2048
#define NROWS 65536
#define NZ (NROWS * DIM)
#define TILE_M 128
#define NCHUNK 64
#define CHUNKS 32
#define KSPLIT 384
#define KSTEPS 24
#define NTH 256

__device__ __align__(16) float g_t[KCODES];
__device__ int   g_idx[NROWS];
__device__ float g_part[1024];
__device__ __align__(16) __half g_bsplit[KCODES * KSPLIT];
__device__ int g_cnt;
__device__ int g_list[NROWS];

// ---- smem byte offsets (stage 1) ----
#define OFF_A    0          // 128 x 384 f16 = 98304
#define OFF_B0   98304      // 64 x 384 f16 = 49152
#define OFF_B1   147456
#define OFF_TALL 196608     // 2048 f32
#define OFF_SROW 204800     // 128 f32
#define OFF_BEST 205312     // 128 f32
#define OFF_IDX  205824     // 128 i32
#define OFF_B2   206336     // 128 f32
#define SMEM_SZ  206848

// ---- PTX helpers (plain sm_80-era; compile for compute_103) ----
static __device__ __forceinline__ void ldsm4(uint32_t& r0, uint32_t& r1,
                                             uint32_t& r2, uint32_t& r3, uint32_t a) {
    asm volatile("ldmatrix.sync.aligned.m8n8.x4.shared.b16 {%0,%1,%2,%3}, [%4];"
                 : "=r"(r0), "=r"(r1), "=r"(r2), "=r"(r3) : "r"(a));
}
static __device__ __forceinline__ void mma16816(float* c, const uint32_t* a,
                                                uint32_t b0, uint32_t b1) {
    asm volatile("mma.sync.aligned.m16n8k16.row.col.f32.f16.f16.f32 "
                 "{%0,%1,%2,%3}, {%4,%5,%6,%7}, {%8,%9}, {%0,%1,%2,%3};"
                 : "+f"(c[0]), "+f"(c[1]), "+f"(c[2]), "+f"(c[3])
                 : "r"(a[0]), "r"(a[1]), "r"(a[2]), "r"(a[3]), "r"(b0), "r"(b1));
}
#define CP_ASYNC16(d, s) asm volatile("cp.async.ca.shared.global [%0], [%1], 16;" :: "r"(d), "l"(s))
#define CP_COMMIT() asm volatile("cp.async.commit_group;" ::: "memory")
#define CP_WAIT0()  asm volatile("cp.async.wait_group 0;" ::: "memory")

__global__ void k_zero() { if (threadIdx.x == 0) g_cnt = 0; }

// ---- prep: ||e||^2 (exact sequential fp32) ----
__global__ void k_embnorm(const float* __restrict__ emb) {
    int j = blockIdx.x * blockDim.x + threadIdx.x;
    if (j < KCODES) {
        const float* e = emb + (size_t)j * DIM;
        float s = 0.f;
        #pragma unroll 8
        for (int k = 0; k < DIM; ++k)
            s = __fadd_rn(s, __fmul_rn(e[k], e[k]));
        g_t[j] = s;
    }
}

// ---- prep: split codebook, scaled by 2048 ----
__global__ void k_split(const float* __restrict__ emb) {
    int idx = blockIdx.x * blockDim.x + threadIdx.x;
    int code = idx >> 7, k = idx & 127;
    float ep = __fmul_rn(emb[(size_t)code * DIM + k], 2048.0f);
    __half g1 = __float2half_rn(ep);
    float r1 = __fsub_rn(ep, __half2float(g1));
    __half g2 = __float2half_rn(r1);
    __half* row = g_bsplit + (size_t)code * KSPLIT;
    row[k] = g1; row[128 + k] = g2; row[256 + k] = g1;
}

// ---- B-chunk async fill ----
static __device__ __forceinline__ void fill_async(uint32_t bBase, int chunk, int tid) {
    const char* src = (const char*)g_bsplit + (size_t)chunk * NCHUNK * 768;
    #pragma unroll
    for (int j = 0; j < 12; ++j) {
        int i = tid + j * NTH;
        int code = i / 48;
        int kg = i - code * 48;
        uint32_t d = bBase + (uint32_t)(code * 768 + (((kg & ~7) | ((kg ^ code) & 7)) << 4));
        CP_ASYNC16(d, src + code * 768 + kg * 16);
    }
    CP_COMMIT();
}

// ---- stage 1: HMMA split-f16 distance GEMM + argmin + top-2 margin flag ----
__global__ __launch_bounds__(NTH, 1)
void k_argmin_tc(const float* __restrict__ z) {
    extern __shared__ char smc[];
    uint32_t sb;
    asm("{ .reg .u64 t; cvta.to.shared.u64 t, %1; cvt.u32.u64 %0, t; }" : "=r"(sb) : "l"(smc));
    float* tall  = (float*)(smc + OFF_TALL);
    float* srow  = (float*)(smc + OFF_SROW);
    float* bestA = (float*)(smc + OFF_BEST);
    int*   idxA  = (int*)(smc + OFF_IDX);
    float* b2A   = (float*)(smc + OFF_B2);

    const int tid = threadIdx.x;
    const int lane = tid & 31, wid = tid >> 5;
    const int wm = wid & 3, wn = wid >> 2;
    const int rbase = blockIdx.x * TILE_M;

    fill_async(sb + OFF_B0, 0, tid);

    for (int i = tid; i < KCODES / 4; i += NTH)
        ((float4*)tall)[i] = ((const float4*)g_t)[i];

    // build A tile: blocks [h1|h1|h2], XOR-swizzled
    {
        int r = tid >> 1, half = tid & 1;
        const float* zr = z + (size_t)(rbase + r) * DIM + half * 64;
        char* arow = smc + OFF_A + r * 768;
        int rx = r & 7;
        #pragma unroll
        for (int g = 0; g < 8; ++g) {
            float4 v0 = *(const float4*)(zr + g * 8);
            float4 v1 = *(const float4*)(zr + g * 8 + 4);
            float f[8] = {v0.x, v0.y, v0.z, v0.w, v1.x, v1.y, v1.z, v1.w};
            uint32_t h1p[4], h2p[4];
            #pragma unroll
            for (int e = 0; e < 4; ++e) {
                __half a = __float2half_rn(f[2 * e]);
                __half b = __float2half_rn(f[2 * e + 1]);
                h1p[e] = (uint32_t)__half_as_ushort(a) | ((uint32_t)__half_as_ushort(b) << 16);
                __half a2 = __float2half_rn(__fsub_rn(f[2 * e], __half2float(a)));
                __half b2 = __float2half_rn(__fsub_rn(f[2 * e + 1], __half2float(b)));
                h2p[e] = (uint32_t)__half_as_ushort(a2) | ((uint32_t)__half_as_ushort(b2) << 16);
            }
            int kg0 = half * 8 + g;
            int ks0 = (kg0 & ~7) | ((kg0 & 7) ^ rx);
            *(uint4*)(arow + ks0 * 16)        = *(uint4*)h1p;
            *(uint4*)(arow + (ks0 + 16) * 16) = *(uint4*)h1p;
            *(uint4*)(arow + (ks0 + 32) * 16) = *(uint4*)h2p;
        }
    }

    if (tid < TILE_M) {
        const float* zr = z + (size_t)(rbase + tid) * DIM;
        float s = 0.f;
        #pragma unroll 8
        for (int k = 0; k < DIM; ++k)
            s = __fadd_rn(s, __fmul_rn(zr[k], zr[k]));
        srow[tid] = s;
    }
    CP_WAIT0();
    __syncthreads();

    const int rx7 = lane & 7;
    const int klane = (lane >> 4) & 1;
    const uint32_t aRow0 = sb + OFF_A +
        (uint32_t)((wm * 32 + (lane & 7) + ((lane & 8) ? 8 : 0)) * 768);
    const uint32_t bRowOff =
        (uint32_t)((wn * 32 + (lane & 7) + ((lane & 8) ? 8 : 0)) * 768);

    float s_r[4]; int rowid[4];
    #pragma unroll
    for (int mi = 0; mi < 2; ++mi)
        #pragma unroll
        for (int h = 0; h < 2; ++h) {
            int rr = wm * 32 + mi * 16 + (lane >> 2) + 8 * h;
            rowid[mi * 2 + h] = rr;
            s_r[mi * 2 + h] = srow[rr];
        }
    float best[4], bsec[4]; int bidx[4];
    #pragma unroll
    for (int s = 0; s < 4; ++s) { best[s] = CUDART_INF_F; bsec[s] = CUDART_INF_F; bidx[s] = 0; }

    for (int c = 0; c < CHUNKS; ++c) {
        if (c + 1 < CHUNKS)
            fill_async(sb + ((c & 1) ? OFF_B0 : OFF_B1), c + 1, tid);
        const uint32_t bBase = sb + ((c & 1) ? OFF_B1 : OFF_B0);

        float acc[2][4][4];
        #pragma unroll
        for (int i = 0; i < 32; ++i) ((float*)acc)[i] = 0.f;

        #pragma unroll 4
        for (int ks = 0; ks < KSTEPS; ++ks) {
            int kg = 2 * ks + klane;
            uint32_t kslot = (uint32_t)(((kg & ~7) | ((kg & 7) ^ rx7)) << 4);
            uint32_t A0[4], A1[4], B0[4], B1[4];
            ldsm4(A0[0], A0[1], A0[2], A0[3], aRow0 + kslot);
            ldsm4(A1[0], A1[1], A1[2], A1[3], aRow0 + 16 * 768 + kslot);
            ldsm4(B0[0], B0[1], B0[2], B0[3], bBase + bRowOff + kslot);
            ldsm4(B1[0], B1[1], B1[2], B1[3], bBase + bRowOff + 16 * 768 + kslot);
            mma16816(acc[0][0], A0, B0[0], B0[2]);
            mma16816(acc[0][1], A0, B0[1], B0[3]);
            mma16816(acc[0][2], A0, B1[0], B1[2]);
            mma16816(acc[0][3], A0, B1[1], B1[3]);
            mma16816(acc[1][0], A1, B0[0], B0[2]);
            mma16816(acc[1][1], A1, B0[1], B0[3]);
            mma16816(acc[1][2], A1, B1[0], B1[2]);
            mma16816(acc[1][3], A1, B1[1], B1[3]);
        }

        const int cb0 = c * NCHUNK + wn * 32 + 2 * (lane & 3);
        #pragma unroll
        for (int mi = 0; mi < 2; ++mi)
            #pragma unroll
            for (int ni = 0; ni < 4; ++ni) {
                const float* cc = acc[mi][ni];
                int code = cb0 + ni * 8;
                float t0 = tall[code], t1 = tall[code + 1];
                #pragma unroll
                for (int h = 0; h < 2; ++h) {
                    int s = mi * 2 + h;
                    float d0 = __fadd_rn(__fsub_rn(s_r[s], __fmul_rn(cc[2 * h],     9.765625e-4f)), t0);
                    float d1 = __fadd_rn(__fsub_rn(s_r[s], __fmul_rn(cc[2 * h + 1], 9.765625e-4f)), t1);
                    if (d0 < best[s]) { bsec[s] = best[s]; best[s] = d0; bidx[s] = code; }
                    else if (d0 < bsec[s]) bsec[s] = d0;
                    if (d1 < best[s]) { bsec[s] = best[s]; best[s] = d1; bidx[s] = code + 1; }
                    else if (d1 < bsec[s]) bsec[s] = d1;
                }
            }

        CP_WAIT0();
        __syncthreads();
    }

    // quad reduce with top-2 merge, tie -> lowest index
    #pragma unroll
    for (int s = 0; s < 4; ++s) {
        float v = best[s], v2 = bsec[s]; int ix = bidx[s];
        #pragma unroll
        for (int off = 2; off > 0; off >>= 1) {
            float o1 = __shfl_down_sync(0xffffffffu, v, off, 4);
            int   oi = __shfl_down_sync(0xffffffffu, ix, off, 4);
            float o2 = __shfl_down_sync(0xffffffffu, v2, off, 4);
            if (o1 < v || (o1 == v && oi < ix)) { v2 = fminf(v, o2); v = o1; ix = oi; }
            else { v2 = fminf(v2, o1); }
        }
        best[s] = v; bsec[s] = v2; bidx[s] = ix;
    }
    if (wn == 0 && (lane & 3) == 0) {
        #pragma unroll
        for (int s = 0; s < 4; ++s) {
            bestA[rowid[s]] = best[s]; idxA[rowid[s]] = bidx[s]; b2A[rowid[s]] = bsec[s];
        }
    }
    __syncthreads();
    if (wn == 1 && (lane & 3) == 0) {
        #pragma unroll
        for (int s = 0; s < 4; ++s) {
            float a1 = bestA[rowid[s]], a2 = b2A[rowid[s]]; int ai = idxA[rowid[s]];
            float c1 = best[s], c2 = bsec[s]; int ci = bidx[s];
            float nb1, nb2; int ni1;
            if (c1 < a1 || (c1 == a1 && ci < ai)) { nb1 = c1; ni1 = ci; nb2 = fminf(a1, c2); }
            else { nb1 = a1; ni1 = ai; nb2 = fminf(a2, c1); }
            int row = rbase + rowid[s];
            g_idx[row] = ni1;
            // flag ambiguous rows (gap within ~2.6 ulp of d) for exact recompute
            float margin = __fmaf_rn(nb1, 3e-7f, 2e-7f);
            if (!(nb2 - nb1 > margin)) {
                int pos = atomicAdd(&g_cnt, 1);
                g_list[pos] = row;
            }
        }
    }
}

// ---- stage 2: exact sequential-fp32 recompute for flagged rows ----
// 16 rows per block; thread = (rsub = tid>>4, clane = tid&15); emb chunk-staged k-major.
__global__ __launch_bounds__(256)
void k_exact(const float* __restrict__ z, const float* __restrict__ emb) {
    __shared__ float zrow[16][DIM];
    __shared__ float es[DIM * 65];   // k-major, stride 65 (conflict-free)
    const int tid = threadIdx.x;
    const int cnt = g_cnt;
    const int rsub = tid >> 4, clane = tid & 15;

    for (int base = blockIdx.x * 16; base < cnt; base += gridDim.x * 16) {
        const int nrows = min(16, cnt - base);
        __syncthreads();
        for (int i = tid; i < nrows * 32; i += 256) {
            int rr = i >> 5, q = i & 31;
            int row = g_list[base + rr];
            ((float4*)zrow[rr])[q] = ((const float4*)(z + (size_t)row * DIM))[q];
        }
        __syncthreads();

        const bool active = rsub < nrows;
        float s = 0.f;
        if (active) {
            #pragma unroll 8
            for (int k = 0; k < DIM; ++k) {
                float v = zrow[rsub][k];
                s = __fadd_rn(s, __fmul_rn(v, v));
            }
        }
        float best = CUDART_INF_F; int bidx = 0;

        for (int ch = 0; ch < CHUNKS; ++ch) {
            __syncthreads();
            // stage 64 codes, coalesced gmem, conflict-free STS via stride-65
            for (int i = tid; i < 64 * 32; i += 256) {
                int cl = i >> 5, q = i & 31;
                float4 v = ((const float4*)(emb + (size_t)(ch * 64 + cl) * DIM))[q];
                es[(q * 4 + 0) * 65 + cl] = v.x;
                es[(q * 4 + 1) * 65 + cl] = v.y;
                es[(q * 4 + 2) * 65 + cl] = v.z;
                es[(q * 4 + 3) * 65 + cl] = v.w;
            }
            __syncthreads();
            if (active) {
                #pragma unroll
                for (int j = 0; j < 4; ++j) {       // codes ascending: clane + 16j
                    int c = clane + 16 * j;
                    float m = 0.f;
                    #pragma unroll 8
                    for (int k = 0; k < DIM; ++k)
                        m = __fmaf_rn(zrow[rsub][k], es[k * 65 + c], m);
                    float d = __fadd_rn(__fsub_rn(s, __fmul_rn(2.f, m)), g_t[ch * 64 + c]);
                    int code = ch * 64 + c;
                    if (d < best) { best = d; bidx = code; }
                }
            }
        }
        // 16-lane reduce (half-warp = one row), tie -> lowest index
        #pragma unroll
        for (int off = 8; off > 0; off >>= 1) {
            float v2 = __shfl_down_sync(0xffffffffu, best, off, 16);
            int   i2 = __shfl_down_sync(0xffffffffu, bidx, off, 16);
            if (v2 < best || (v2 == best && i2 < bidx)) { best = v2; bidx = i2; }
        }
        if (active && clane == 0)
            g_idx[g_list[base + rsub]] = bidx;
    }
}

// ---- gather + straight-through + indices + loss partials ----
__global__ __launch_bounds__(256)
void k_out(const float* __restrict__ z, const float* __restrict__ emb,
           float* __restrict__ out, long long out_size) {
    __shared__ float red[256];
    const int tid = threadIdx.x;
    const long long row0 = (long long)blockIdx.x * 64;
    float lsum = 0.f;

    for (int i = tid; i < 64 * (DIM / 4); i += 256) {
        long long r  = row0 + (i >> 5);
        int       d4 = (i & 31) * 4;
        int idx = g_idx[r];
        float4 q  = *(const float4*)(emb + (size_t)idx * DIM + d4);
        long long gi = r * DIM + d4;
        float4 zz = *(const float4*)(z + gi);
        float4 o; float df;
        df = __fsub_rn(q.x, zz.x); o.x = __fadd_rn(zz.x, df); lsum += df * df;
        df = __fsub_rn(q.y, zz.y); o.y = __fadd_rn(zz.y, df); lsum += df * df;
        df = __fsub_rn(q.z, zz.z); o.z = __fadd_rn(zz.z, df); lsum += df * df;
        df = __fsub_rn(q.w, zz.w); o.w = __fadd_rn(zz.w, df); lsum += df * df;
        if (gi + 3 < out_size) *(float4*)(out + gi) = o;
    }

    if (tid < 64) {
        long long r  = row0 + tid;
        long long gi = (long long)NZ + r;
        if (gi < out_size) out[gi] = (float)g_idx[r];
    }

    red[tid] = lsum;
    __syncthreads();
    for (int s = 128; s > 0; s >>= 1) {
        if (tid < s) red[tid] += red[tid + s];
        __syncthreads();
    }
    if (tid == 0) g_part[blockIdx.x] = red[0];
}

// ---- deterministic final loss reduce ----
__global__ void k_final(float* __restrict__ out, long long out_size) {
    __shared__ float red[256];
    const int tid = threadIdx.x;
    float s = 0.f;
    for (int i = tid; i < 1024; i += 256) s += g_part[i];
    red[tid] = s;
    __syncthreads();
    for (int w = 128; w > 0; w >>= 1) {
        if (tid < w) red[tid] += red[tid + w];
        __syncthreads();
    }
    if (tid == 0) {
        float m = red[0] / (float)NZ;
        float loss = __fadd_rn(m, __fmul_rn(0.25f, m));
        long long li = (long long)NZ + NROWS;
        if (li < out_size) out[li] = loss;
    }
}

extern "C" void kernel_launch(void* const* d_in, const int* in_sizes, int n_in,
                              void* d_out, int out_size) {
    const float* z   = (const float*)d_in[0];
    const float* emb = (const float*)d_in[1];
    float* out = (float*)d_out;

    cudaFuncSetAttribute(k_argmin_tc, cudaFuncAttributeMaxDynamicSharedMemorySize, SMEM_SZ);

    k_zero<<<1, 32>>>();
    k_embnorm<<<(KCODES + 255) / 256, 256>>>(emb);
    k_split<<<(KCODES * DIM) / 256, 256>>>(emb);
    k_argmin_tc<<<NROWS / TILE_M, NTH, SMEM_SZ>>>(z);
    k_exact<<<256, 256>>>(z, emb);
    k_out<<<NROWS / 64, 256>>>(z, emb, out, (long long)out_size);
    k_final<<<1, 256>>>(out, (long long)out_size);
}

// round 9
// speedup vs baseline: 1.9657x; 1.0158x over previous
#include <cuda_runtime.h>
#include <cuda_fp16.h>
#include <math_constants.h>
#include <cstdint>

#define DIM 128
#define KCODES 2048
#define NROWS 65536
#define NZ (NROWS * DIM)
#define TILE_M 128
#define NCHUNK 64
#define CHUNKS 32
#define KSTEPS 24
#define NTH 256

__device__ __align__(16) float g_t[KCODES];
__device__ int   g_idx[NROWS];
__device__ float g_part[1024];
__device__ __align__(16) __half g_bsplit[KCODES * 256];   // [g1'|g2'] per code, e' = 2048*e
__device__ int g_cnt;
__device__ int g_list[NROWS];

// ---- smem byte offsets (stage 1) ----
#define OFF_A    0          // 128 rows x 256 f16 ([h1|h2]) = 65536
#define OFF_B    65536      // 4 buffers x (64 codes x 512B) = 131072
#define BUFSZ    32768
#define OFF_TALL 196608     // 2048 f32
#define OFF_SROW 204800     // 128 f32
#define OFF_BEST 205312
#define OFF_IDX  205824
#define OFF_B2   206336
#define SMEM_SZ  206848

// ---- PTX helpers ----
static __device__ __forceinline__ void ldsm4(uint32_t& r0, uint32_t& r1,
                                             uint32_t& r2, uint32_t& r3, uint32_t a) {
    asm volatile("ldmatrix.sync.aligned.m8n8.x4.shared.b16 {%0,%1,%2,%3}, [%4];"
                 : "=r"(r0), "=r"(r1), "=r"(r2), "=r"(r3) : "r"(a));
}
static __device__ __forceinline__ void mma16816(float* c, const uint32_t* a,
                                                uint32_t b0, uint32_t b1) {
    asm volatile("mma.sync.aligned.m16n8k16.row.col.f32.f16.f16.f32 "
                 "{%0,%1,%2,%3}, {%4,%5,%6,%7}, {%8,%9}, {%0,%1,%2,%3};"
                 : "+f"(c[0]), "+f"(c[1]), "+f"(c[2]), "+f"(c[3])
                 : "r"(a[0]), "r"(a[1]), "r"(a[2]), "r"(a[3]), "r"(b0), "r"(b1));
}
#define CP_ASYNC16(d, s) asm volatile("cp.async.ca.shared.global [%0], [%1], 16;" :: "r"(d), "l"(s))
#define CP_COMMIT() asm volatile("cp.async.commit_group;" ::: "memory")
#define CP_WAIT0()  asm volatile("cp.async.wait_group 0;" ::: "memory")
#define CP_WAIT1()  asm volatile("cp.async.wait_group 1;" ::: "memory")
#define CP_WAIT2()  asm volatile("cp.async.wait_group 2;" ::: "memory")

__global__ void k_zero() { if (threadIdx.x == 0) g_cnt = 0; }

// ---- prep: ||e||^2 (exact sequential fp32) ----
__global__ void k_embnorm(const float* __restrict__ emb) {
    int j = blockIdx.x * blockDim.x + threadIdx.x;
    if (j < KCODES) {
        const float* e = emb + (size_t)j * DIM;
        float s = 0.f;
        #pragma unroll 8
        for (int k = 0; k < DIM; ++k)
            s = __fadd_rn(s, __fmul_rn(e[k], e[k]));
        g_t[j] = s;
    }
}

// ---- prep: split codebook [g1|g2], scaled by 2048 ----
__global__ void k_split(const float* __restrict__ emb) {
    int idx = blockIdx.x * blockDim.x + threadIdx.x;
    int code = idx >> 7, k = idx & 127;
    float ep = __fmul_rn(emb[(size_t)code * DIM + k], 2048.0f);
    __half g1 = __float2half_rn(ep);
    float r1 = __fsub_rn(ep, __half2float(g1));
    __half g2 = __float2half_rn(r1);
    __half* row = g_bsplit + (size_t)code * 256;
    row[k] = g1; row[128 + k] = g2;
}

// ---- B-chunk async fill: 64 codes x 32 16B-groups, XOR-swizzled ----
static __device__ __forceinline__ void fill_async(uint32_t bBase, int chunk, int tid) {
    const char* src = (const char*)g_bsplit + (size_t)chunk * NCHUNK * 512;
    #pragma unroll
    for (int j = 0; j < 8; ++j) {
        int i = tid + j * NTH;             // < 2048
        int code = i >> 5;
        int kg = i & 31;
        uint32_t d = bBase + (uint32_t)(code * 512 + (((kg & ~7) | ((kg ^ code) & 7)) << 4));
        CP_ASYNC16(d, src + code * 512 + kg * 16);
    }
    CP_COMMIT();
}

// ---- stage 1: HMMA split-f16 distance GEMM + argmin + top-2 margin flag ----
__global__ __launch_bounds__(NTH, 1)
void k_argmin_tc(const float* __restrict__ z) {
    extern __shared__ char smc[];
    uint32_t sb;
    asm("{ .reg .u64 t; cvta.to.shared.u64 t, %1; cvt.u32.u64 %0, t; }" : "=r"(sb) : "l"(smc));
    float* tall  = (float*)(smc + OFF_TALL);
    float* srow  = (float*)(smc + OFF_SROW);
    float* bestA = (float*)(smc + OFF_BEST);
    int*   idxA  = (int*)(smc + OFF_IDX);
    float* b2A   = (float*)(smc + OFF_B2);

    const int tid = threadIdx.x;
    const int lane = tid & 31, wid = tid >> 5;
    const int wm = wid & 3, wn = wid >> 2;
    const int rbase = blockIdx.x * TILE_M;

    // prologue: 3 chunk fills in flight
    fill_async(sb + OFF_B + 0 * BUFSZ, 0, tid);
    fill_async(sb + OFF_B + 1 * BUFSZ, 1, tid);
    fill_async(sb + OFF_B + 2 * BUFSZ, 2, tid);

    for (int i = tid; i < KCODES / 4; i += NTH)
        ((float4*)tall)[i] = ((const float4*)g_t)[i];

    // build A tile [h1|h2], row stride 512B, XOR-swizzled
    {
        int r = tid >> 1, half = tid & 1;
        const float* zr = z + (size_t)(rbase + r) * DIM + half * 64;
        char* arow = smc + OFF_A + r * 512;
        int rx = r & 7;
        #pragma unroll
        for (int g = 0; g < 8; ++g) {
            float4 v0 = *(const float4*)(zr + g * 8);
            float4 v1 = *(const float4*)(zr + g * 8 + 4);
            float f[8] = {v0.x, v0.y, v0.z, v0.w, v1.x, v1.y, v1.z, v1.w};
            uint32_t h1p[4], h2p[4];
            #pragma unroll
            for (int e = 0; e < 4; ++e) {
                __half a = __float2half_rn(f[2 * e]);
                __half b = __float2half_rn(f[2 * e + 1]);
                h1p[e] = (uint32_t)__half_as_ushort(a) | ((uint32_t)__half_as_ushort(b) << 16);
                __half a2 = __float2half_rn(__fsub_rn(f[2 * e], __half2float(a)));
                __half b2 = __float2half_rn(__fsub_rn(f[2 * e + 1], __half2float(b)));
                h2p[e] = (uint32_t)__half_as_ushort(a2) | ((uint32_t)__half_as_ushort(b2) << 16);
            }
            int kg0 = half * 8 + g;                         // 0..15 (h1 region)
            int ks0 = (kg0 & ~7) | ((kg0 & 7) ^ rx);
            *(uint4*)(arow + ks0 * 16)        = *(uint4*)h1p;   // h1 at groups 0..15
            *(uint4*)(arow + (ks0 + 16) * 16) = *(uint4*)h2p;   // h2 at groups 16..31
        }
    }

    if (tid < TILE_M) {
        const float* zr = z + (size_t)(rbase + tid) * DIM;
        float s = 0.f;
        #pragma unroll 8
        for (int k = 0; k < DIM; ++k)
            s = __fadd_rn(s, __fmul_rn(zr[k], zr[k]));
        srow[tid] = s;
    }
    __syncthreads();

    const int rx7 = lane & 7;
    const int klane = (lane >> 4) & 1;
    const uint32_t aRow0 = sb + OFF_A +
        (uint32_t)((wm * 32 + (lane & 7) + ((lane & 8) ? 8 : 0)) * 512);
    const uint32_t bRowOff =
        (uint32_t)((wn * 32 + (lane & 7) + ((lane & 8) ? 8 : 0)) * 512);

    float s_r[4]; int rowid[4];
    #pragma unroll
    for (int mi = 0; mi < 2; ++mi)
        #pragma unroll
        for (int h = 0; h < 2; ++h) {
            int rr = wm * 32 + mi * 16 + (lane >> 2) + 8 * h;
            rowid[mi * 2 + h] = rr;
            s_r[mi * 2 + h] = srow[rr];
        }
    float best[4], bsec[4]; int bidx[4];
    #pragma unroll
    for (int s = 0; s < 4; ++s) { best[s] = CUDART_INF_F; bsec[s] = CUDART_INF_F; bidx[s] = 0; }

    for (int c = 0; c < CHUNKS; ++c) {
        // ensure group c complete (pending allowance shrinks at the tail)
        if (c < 30) CP_WAIT2(); else if (c == 30) CP_WAIT1(); else CP_WAIT0();
        __syncthreads();   // all threads' copies visible; all warps done with buf[(c-1)&3]
        if (c + 3 < CHUNKS)
            fill_async(sb + OFF_B + ((c + 3) & 3) * BUFSZ, c + 3, tid);

        const uint32_t bBase = sb + OFF_B + (c & 3) * BUFSZ;

        float acc[2][4][4];
        #pragma unroll
        for (int i = 0; i < 32; ++i) ((float*)acc)[i] = 0.f;

        // K order: s 0-7 = h1*g1, 8-15 = h1*g2, 16-23 = h2*g1 (same sums as before)
        #pragma unroll
        for (int s = 0; s < KSTEPS; ++s) {
            const int ab = (s >= 16) ? 16 : 0;                 // A group base
            const int bb = (s >= 8 && s < 16) ? 16 : 0;        // B group base
            const int sk2 = (s & 7) * 2;
            const int Ca = ab + sk2, Cb = bb + sk2;
            uint32_t slotA = (uint32_t)(((Ca & ~7) | (((Ca & 7) + klane) ^ rx7)) << 4);
            uint32_t slotB = (uint32_t)(((Cb & ~7) | (((Cb & 7) + klane) ^ rx7)) << 4);
            uint32_t A0[4], A1[4], B0[4], B1[4];
            ldsm4(A0[0], A0[1], A0[2], A0[3], aRow0 + slotA);
            ldsm4(A1[0], A1[1], A1[2], A1[3], aRow0 + 16 * 512 + slotA);
            ldsm4(B0[0], B0[1], B0[2], B0[3], bBase + bRowOff + slotB);
            ldsm4(B1[0], B1[1], B1[2], B1[3], bBase + bRowOff + 16 * 512 + slotB);
            mma16816(acc[0][0], A0, B0[0], B0[2]);
            mma16816(acc[0][1], A0, B0[1], B0[3]);
            mma16816(acc[0][2], A0, B1[0], B1[2]);
            mma16816(acc[0][3], A0, B1[1], B1[3]);
            mma16816(acc[1][0], A1, B0[0], B0[2]);
            mma16816(acc[1][1], A1, B0[1], B0[3]);
            mma16816(acc[1][2], A1, B1[0], B1[2]);
            mma16816(acc[1][3], A1, B1[1], B1[3]);
        }

        const int cb0 = c * NCHUNK + wn * 32 + 2 * (lane & 3);
        #pragma unroll
        for (int mi = 0; mi < 2; ++mi)
            #pragma unroll
            for (int ni = 0; ni < 4; ++ni) {
                const float* cc = acc[mi][ni];
                int code = cb0 + ni * 8;
                float t0 = tall[code], t1 = tall[code + 1];
                #pragma unroll
                for (int h = 0; h < 2; ++h) {
                    int s = mi * 2 + h;
                    float d0 = __fadd_rn(__fsub_rn(s_r[s], __fmul_rn(cc[2 * h],     9.765625e-4f)), t0);
                    float d1 = __fadd_rn(__fsub_rn(s_r[s], __fmul_rn(cc[2 * h + 1], 9.765625e-4f)), t1);
                    if (d0 < best[s]) { bsec[s] = best[s]; best[s] = d0; bidx[s] = code; }
                    else if (d0 < bsec[s]) bsec[s] = d0;
                    if (d1 < best[s]) { bsec[s] = best[s]; best[s] = d1; bidx[s] = code + 1; }
                    else if (d1 < bsec[s]) bsec[s] = d1;
                }
            }
    }

    // quad reduce with top-2 merge, tie -> lowest index
    #pragma unroll
    for (int s = 0; s < 4; ++s) {
        float v = best[s], v2 = bsec[s]; int ix = bidx[s];
        #pragma unroll
        for (int off = 2; off > 0; off >>= 1) {
            float o1 = __shfl_down_sync(0xffffffffu, v, off, 4);
            int   oi = __shfl_down_sync(0xffffffffu, ix, off, 4);
            float o2 = __shfl_down_sync(0xffffffffu, v2, off, 4);
            if (o1 < v || (o1 == v && oi < ix)) { v2 = fminf(v, o2); v = o1; ix = oi; }
            else { v2 = fminf(v2, o1); }
        }
        best[s] = v; bsec[s] = v2; bidx[s] = ix;
    }
    if (wn == 0 && (lane & 3) == 0) {
        #pragma unroll
        for (int s = 0; s < 4; ++s) {
            bestA[rowid[s]] = best[s]; idxA[rowid[s]] = bidx[s]; b2A[rowid[s]] = bsec[s];
        }
    }
    __syncthreads();
    if (wn == 1 && (lane & 3) == 0) {
        #pragma unroll
        for (int s = 0; s < 4; ++s) {
            float a1 = bestA[rowid[s]], a2 = b2A[rowid[s]]; int ai = idxA[rowid[s]];
            float c1 = best[s], c2 = bsec[s]; int ci = bidx[s];
            float nb1, nb2; int ni1;
            if (c1 < a1 || (c1 == a1 && ci < ai)) { nb1 = c1; ni1 = ci; nb2 = fminf(a1, c2); }
            else { nb1 = a1; ni1 = ai; nb2 = fminf(a2, c1); }
            int row = rbase + rowid[s];
            g_idx[row] = ni1;
            float margin = __fmaf_rn(nb1, 3e-7f, 2e-7f);
            if (!(nb2 - nb1 > margin)) {
                int pos = atomicAdd(&g_cnt, 1);
                g_list[pos] = row;
            }
        }
    }
}

// ---- stage 2: exact sequential-fp32 recompute for flagged rows ----
__global__ __launch_bounds__(256)
void k_exact(const float* __restrict__ z, const float* __restrict__ emb) {
    __shared__ float zrow[16][DIM];
    __shared__ float es[DIM * 65];
    const int tid = threadIdx.x;
    const int cnt = g_cnt;
    const int rsub = tid >> 4, clane = tid & 15;

    for (int base = blockIdx.x * 16; base < cnt; base += gridDim.x * 16) {
        const int nrows = min(16, cnt - base);
        __syncthreads();
        for (int i = tid; i < nrows * 32; i += 256) {
            int rr = i >> 5, q = i & 31;
            int row = g_list[base + rr];
            ((float4*)zrow[rr])[q] = ((const float4*)(z + (size_t)row * DIM))[q];
        }
        __syncthreads();

        const bool active = rsub < nrows;
        float s = 0.f;
        if (active) {
            #pragma unroll 8
            for (int k = 0; k < DIM; ++k) {
                float v = zrow[rsub][k];
                s = __fadd_rn(s, __fmul_rn(v, v));
            }
        }
        float best = CUDART_INF_F; int bidx = 0;

        for (int ch = 0; ch < CHUNKS; ++ch) {
            __syncthreads();
            for (int i = tid; i < 64 * 32; i += 256) {
                int cl = i >> 5, q = i & 31;
                float4 v = ((const float4*)(emb + (size_t)(ch * 64 + cl) * DIM))[q];
                es[(q * 4 + 0) * 65 + cl] = v.x;
                es[(q * 4 + 1) * 65 + cl] = v.y;
                es[(q * 4 + 2) * 65 + cl] = v.z;
                es[(q * 4 + 3) * 65 + cl] = v.w;
            }
            __syncthreads();
            if (active) {
                #pragma unroll
                for (int j = 0; j < 4; ++j) {
                    int c = clane + 16 * j;
                    float m = 0.f;
                    #pragma unroll 8
                    for (int k = 0; k < DIM; ++k)
                        m = __fmaf_rn(zrow[rsub][k], es[k * 65 + c], m);
                    float d = __fadd_rn(__fsub_rn(s, __fmul_rn(2.f, m)), g_t[ch * 64 + c]);
                    int code = ch * 64 + c;
                    if (d < best) { best = d; bidx = code; }
                }
            }
        }
        #pragma unroll
        for (int off = 8; off > 0; off >>= 1) {
            float v2 = __shfl_down_sync(0xffffffffu, best, off, 16);
            int   i2 = __shfl_down_sync(0xffffffffu, bidx, off, 16);
            if (v2 < best || (v2 == best && i2 < bidx)) { best = v2; bidx = i2; }
        }
        if (active && clane == 0)
            g_idx[g_list[base + rsub]] = bidx;
    }
}

// ---- gather + straight-through + indices + loss partials ----
__global__ __launch_bounds__(256)
void k_out(const float* __restrict__ z, const float* __restrict__ emb,
           float* __restrict__ out, long long out_size) {
    __shared__ float red[256];
    const int tid = threadIdx.x;
    const long long row0 = (long long)blockIdx.x * 64;
    float lsum = 0.f;

    for (int i = tid; i < 64 * (DIM / 4); i += 256) {
        long long r  = row0 + (i >> 5);
        int       d4 = (i & 31) * 4;
        int idx = g_idx[r];
        float4 q  = *(const float4*)(emb + (size_t)idx * DIM + d4);
        long long gi = r * DIM + d4;
        float4 zz = *(const float4*)(z + gi);
        float4 o; float df;
        df = __fsub_rn(q.x, zz.x); o.x = __fadd_rn(zz.x, df); lsum += df * df;
        df = __fsub_rn(q.y, zz.y); o.y = __fadd_rn(zz.y, df); lsum += df * df;
        df = __fsub_rn(q.z, zz.z); o.z = __fadd_rn(zz.z, df); lsum += df * df;
        df = __fsub_rn(q.w, zz.w); o.w = __fadd_rn(zz.w, df); lsum += df * df;
        if (gi + 3 < out_size) *(float4*)(out + gi) = o;
    }

    if (tid < 64) {
        long long r  = row0 + tid;
        long long gi = (long long)NZ + r;
        if (gi < out_size) out[gi] = (float)g_idx[r];
    }

    red[tid] = lsum;
    __syncthreads();
    for (int s = 128; s > 0; s >>= 1) {
        if (tid < s) red[tid] += red[tid + s];
        __syncthreads();
    }
    if (tid == 0) g_part[blockIdx.x] = red[0];
}

// ---- deterministic final loss reduce ----
__global__ void k_final(float* __restrict__ out, long long out_size) {
    __shared__ float red[256];
    const int tid = threadIdx.x;
    float s = 0.f;
    for (int i = tid; i < 1024; i += 256) s += g_part[i];
    red[tid] = s;
    __syncthreads();
    for (int w = 128; w > 0; w >>= 1) {
        if (tid < w) red[tid] += red[tid + w];
        __syncthreads();
    }
    if (tid == 0) {
        float m = red[0] / (float)NZ;
        float loss = __fadd_rn(m, __fmul_rn(0.25f, m));
        long long li = (long long)NZ + NROWS;
        if (li < out_size) out[li] = loss;
    }
}

extern "C" void kernel_launch(void* const* d_in, const int* in_sizes, int n_in,
                              void* d_out, int out_size) {
    const float* z   = (const float*)d_in[0];
    const float* emb = (const float*)d_in[1];
    float* out = (float*)d_out;

    cudaFuncSetAttribute(k_argmin_tc, cudaFuncAttributeMaxDynamicSharedMemorySize, SMEM_SZ);

    k_zero<<<1, 32>>>();
    k_embnorm<<<(KCODES + 255) / 256, 256>>>(emb);
    k_split<<<(KCODES * DIM) / 256, 256>>>(emb);
    k_argmin_tc<<<NROWS / TILE_M, NTH, SMEM_SZ>>>(z);
    k_exact<<<256, 256>>>(z, emb);
    k_out<<<NROWS / 64, 256>>>(z, emb, out, (long long)out_size);
    k_final<<<1, 256>>>(out, (long long)out_size);
}

// round 10
// speedup vs baseline: 2.2853x; 1.1626x over previous
#include <cuda_runtime.h>
#include <cuda_fp16.h>
#include <math_constants.h>
#include <cstdint>

#define DIM 128
#define KCODES 2048
#define NROWS 65536
#define NZ (NROWS * DIM)
#define TILE_M 128
#define CHUNK 32
#define CHUNKS 64
#define NTH 256

__device__ __align__(16) float g_t[KCODES];
__device__ int   g_idx[NROWS];
__device__ float g_part[1024];
__device__ __align__(16) __half g_bsplit[KCODES * 256];   // [g1'|g2'] per code, e' = 2048*e
__device__ int g_cnt;
__device__ int g_list[NROWS];

// ---- smem byte offsets (stage 1): total 106 KB -> 2 CTAs/SM ----
#define OFF_A    0          // 128 rows x 512B ([h1|h2]) = 65536
#define OFF_B    65536      // 2 buffers x (32 codes x 512B) = 32768
#define BUFSZ    16384
#define OFF_TALL 98304      // 2048 f32 = 8192
#define OFF_SROW 106496     // 128 f32
#define OFF_BEST 107008
#define OFF_IDX  107520
#define OFF_B2   108032
#define SMEM_SZ  108544

// ---- PTX helpers ----
static __device__ __forceinline__ void ldsm4(uint32_t& r0, uint32_t& r1,
                                             uint32_t& r2, uint32_t& r3, uint32_t a) {
    asm volatile("ldmatrix.sync.aligned.m8n8.x4.shared.b16 {%0,%1,%2,%3}, [%4];"
                 : "=r"(r0), "=r"(r1), "=r"(r2), "=r"(r3) : "r"(a));
}
static __device__ __forceinline__ void mma16816(float* c, const uint32_t* a,
                                                uint32_t b0, uint32_t b1) {
    asm volatile("mma.sync.aligned.m16n8k16.row.col.f32.f16.f16.f32 "
                 "{%0,%1,%2,%3}, {%4,%5,%6,%7}, {%8,%9}, {%0,%1,%2,%3};"
                 : "+f"(c[0]), "+f"(c[1]), "+f"(c[2]), "+f"(c[3])
                 : "r"(a[0]), "r"(a[1]), "r"(a[2]), "r"(a[3]), "r"(b0), "r"(b1));
}
#define CP_ASYNC16(d, s) asm volatile("cp.async.ca.shared.global [%0], [%1], 16;" :: "r"(d), "l"(s))
#define CP_COMMIT() asm volatile("cp.async.commit_group;" ::: "memory")
#define CP_WAIT0()  asm volatile("cp.async.wait_group 0;" ::: "memory")
#define CP_WAIT1()  asm volatile("cp.async.wait_group 1;" ::: "memory")

__global__ void k_zero() { if (threadIdx.x == 0) g_cnt = 0; }

// ---- prep: ||e||^2 (exact sequential fp32) ----
__global__ void k_embnorm(const float* __restrict__ emb) {
    int j = blockIdx.x * blockDim.x + threadIdx.x;
    if (j < KCODES) {
        const float* e = emb + (size_t)j * DIM;
        float s = 0.f;
        #pragma unroll 8
        for (int k = 0; k < DIM; ++k)
            s = __fadd_rn(s, __fmul_rn(e[k], e[k]));
        g_t[j] = s;
    }
}

// ---- prep: split codebook [g1|g2], scaled by 2048 ----
__global__ void k_split(const float* __restrict__ emb) {
    int idx = blockIdx.x * blockDim.x + threadIdx.x;
    int code = idx >> 7, k = idx & 127;
    float ep = __fmul_rn(emb[(size_t)code * DIM + k], 2048.0f);
    __half g1 = __float2half_rn(ep);
    float r1 = __fsub_rn(ep, __half2float(g1));
    __half g2 = __float2half_rn(r1);
    __half* row = g_bsplit + (size_t)code * 256;
    row[k] = g1; row[128 + k] = g2;
}

// ---- B-chunk async fill: 32 codes x 32 16B-units, XOR-swizzled ----
static __device__ __forceinline__ void fill_async(uint32_t bBase, int chunk, int tid) {
    const char* src = (const char*)g_bsplit + (size_t)chunk * CHUNK * 512;
    #pragma unroll
    for (int j = 0; j < 4; ++j) {
        int i = tid + j * NTH;             // < 1024
        int code = i >> 5;
        int kg = i & 31;
        uint32_t d = bBase + (uint32_t)(code * 512 + (((kg & ~7) | ((kg ^ code) & 7)) << 4));
        CP_ASYNC16(d, src + code * 512 + kg * 16);
    }
    CP_COMMIT();
}

// ---- stage 1: HMMA split-f16 distance GEMM + argmin + top-2 margin flag ----
// 2 CTAs/SM. Fragment-reuse mainloop: per k-group load {A_h1,A_h2,B_g1,B_g2} once (6 ldsm),
// issue all 12 mma (h1g1, h1g2, h2g1).
__global__ __launch_bounds__(NTH, 2)
void k_argmin_tc(const float* __restrict__ z) {
    extern __shared__ char smc[];
    uint32_t sb;
    asm("{ .reg .u64 t; cvta.to.shared.u64 t, %1; cvt.u32.u64 %0, t; }" : "=r"(sb) : "l"(smc));
    float* tall  = (float*)(smc + OFF_TALL);
    float* srow  = (float*)(smc + OFF_SROW);
    float* bestA = (float*)(smc + OFF_BEST);
    int*   idxA  = (int*)(smc + OFF_IDX);
    float* b2A   = (float*)(smc + OFF_B2);

    const int tid = threadIdx.x;
    const int lane = tid & 31, wid = tid >> 5;
    const int wm = wid & 3, wn = wid >> 2;
    const int rbase = blockIdx.x * TILE_M;

    // prologue: 2 chunk fills in flight
    fill_async(sb + OFF_B + 0 * BUFSZ, 0, tid);
    fill_async(sb + OFF_B + 1 * BUFSZ, 1, tid);

    for (int i = tid; i < KCODES / 4; i += NTH)
        ((float4*)tall)[i] = ((const float4*)g_t)[i];

    // build A tile [h1|h2], row stride 512B, XOR-swizzled
    {
        int r = tid >> 1, half = tid & 1;
        const float* zr = z + (size_t)(rbase + r) * DIM + half * 64;
        char* arow = smc + OFF_A + r * 512;
        int rx = r & 7;
        #pragma unroll
        for (int g = 0; g < 8; ++g) {
            float4 v0 = *(const float4*)(zr + g * 8);
            float4 v1 = *(const float4*)(zr + g * 8 + 4);
            float f[8] = {v0.x, v0.y, v0.z, v0.w, v1.x, v1.y, v1.z, v1.w};
            uint32_t h1p[4], h2p[4];
            #pragma unroll
            for (int e = 0; e < 4; ++e) {
                __half a = __float2half_rn(f[2 * e]);
                __half b = __float2half_rn(f[2 * e + 1]);
                h1p[e] = (uint32_t)__half_as_ushort(a) | ((uint32_t)__half_as_ushort(b) << 16);
                __half a2 = __float2half_rn(__fsub_rn(f[2 * e], __half2float(a)));
                __half b2 = __float2half_rn(__fsub_rn(f[2 * e + 1], __half2float(b)));
                h2p[e] = (uint32_t)__half_as_ushort(a2) | ((uint32_t)__half_as_ushort(b2) << 16);
            }
            int kg0 = half * 8 + g;
            int ks0 = (kg0 & ~7) | ((kg0 & 7) ^ rx);
            *(uint4*)(arow + ks0 * 16)        = *(uint4*)h1p;   // h1: units 0..15
            *(uint4*)(arow + (ks0 + 16) * 16) = *(uint4*)h2p;   // h2: units 16..31
        }
    }

    if (tid < TILE_M) {
        const float* zr = z + (size_t)(rbase + tid) * DIM;
        float s = 0.f;
        #pragma unroll 8
        for (int k = 0; k < DIM; ++k)
            s = __fadd_rn(s, __fmul_rn(zr[k], zr[k]));
        srow[tid] = s;
    }
    __syncthreads();

    const int rx7 = lane & 7;
    const int klane = (lane >> 4) & 1;
    const uint32_t aRow0 = sb + OFF_A +
        (uint32_t)((wm * 32 + (lane & 7) + ((lane & 8) ? 8 : 0)) * 512);
    const uint32_t bRowOff =
        (uint32_t)((wn * 16 + (lane & 7) + ((lane & 8) ? 8 : 0)) * 512);

    float s_r[4]; int rowid[4];
    #pragma unroll
    for (int mi = 0; mi < 2; ++mi)
        #pragma unroll
        for (int h = 0; h < 2; ++h) {
            int rr = wm * 32 + mi * 16 + (lane >> 2) + 8 * h;
            rowid[mi * 2 + h] = rr;
            s_r[mi * 2 + h] = srow[rr];
        }
    float best[4], bsec[4]; int bidx[4];
    #pragma unroll
    for (int s = 0; s < 4; ++s) { best[s] = CUDART_INF_F; bsec[s] = CUDART_INF_F; bidx[s] = 0; }

    for (int c = 0; c < CHUNKS; ++c) {
        if (c < CHUNKS - 1) CP_WAIT1(); else CP_WAIT0();
        __syncthreads();   // fill(c) visible to all warps
        const uint32_t bBase = sb + OFF_B + (c & 1) * BUFSZ;

        float acc[2][2][4];
        #pragma unroll
        for (int i = 0; i < 16; ++i) ((float*)acc)[i] = 0.f;

        #pragma unroll
        for (int kk = 0; kk < 8; ++kk) {
            const int C1 = kk * 2 + klane;        // h1 / g1 unit
            const int C2 = C1 + 16;               // h2 / g2 unit
            const uint32_t slot1 = (uint32_t)(((C1 & ~7) | ((C1 & 7) ^ rx7)) << 4);
            const uint32_t slot2 = (uint32_t)(((C2 & ~7) | ((C2 & 7) ^ rx7)) << 4);
            uint32_t A0h1[4], A1h1[4], A0h2[4], A1h2[4], Bg1[4], Bg2[4];
            ldsm4(A0h1[0], A0h1[1], A0h1[2], A0h1[3], aRow0 + slot1);
            ldsm4(A1h1[0], A1h1[1], A1h1[2], A1h1[3], aRow0 + 16 * 512 + slot1);
            ldsm4(A0h2[0], A0h2[1], A0h2[2], A0h2[3], aRow0 + slot2);
            ldsm4(A1h2[0], A1h2[1], A1h2[2], A1h2[3], aRow0 + 16 * 512 + slot2);
            ldsm4(Bg1[0], Bg1[1], Bg1[2], Bg1[3], bBase + bRowOff + slot1);
            ldsm4(Bg2[0], Bg2[1], Bg2[2], Bg2[3], bBase + bRowOff + slot2);
            // h1*g1
            mma16816(acc[0][0], A0h1, Bg1[0], Bg1[2]);
            mma16816(acc[0][1], A0h1, Bg1[1], Bg1[3]);
            mma16816(acc[1][0], A1h1, Bg1[0], Bg1[2]);
            mma16816(acc[1][1], A1h1, Bg1[1], Bg1[3]);
            // h1*g2
            mma16816(acc[0][0], A0h1, Bg2[0], Bg2[2]);
            mma16816(acc[0][1], A0h1, Bg2[1], Bg2[3]);
            mma16816(acc[1][0], A1h1, Bg2[0], Bg2[2]);
            mma16816(acc[1][1], A1h1, Bg2[1], Bg2[3]);
            // h2*g1
            mma16816(acc[0][0], A0h2, Bg1[0], Bg1[2]);
            mma16816(acc[0][1], A0h2, Bg1[1], Bg1[3]);
            mma16816(acc[1][0], A1h2, Bg1[0], Bg1[2]);
            mma16816(acc[1][1], A1h2, Bg1[1], Bg1[3]);
        }

        // epilogue: d = fl(fl(s - acc/1024) + t); ascending codes; strict <
        const int cb0 = c * CHUNK + wn * 16 + 2 * (lane & 3);
        #pragma unroll
        for (int mi = 0; mi < 2; ++mi)
            #pragma unroll
            for (int ni = 0; ni < 2; ++ni) {
                const float* cc = acc[mi][ni];
                int code = cb0 + ni * 8;
                float t0 = tall[code], t1 = tall[code + 1];
                #pragma unroll
                for (int h = 0; h < 2; ++h) {
                    int s = mi * 2 + h;
                    float d0 = __fadd_rn(__fsub_rn(s_r[s], __fmul_rn(cc[2 * h],     9.765625e-4f)), t0);
                    float d1 = __fadd_rn(__fsub_rn(s_r[s], __fmul_rn(cc[2 * h + 1], 9.765625e-4f)), t1);
                    if (d0 < best[s]) { bsec[s] = best[s]; best[s] = d0; bidx[s] = code; }
                    else if (d0 < bsec[s]) bsec[s] = d0;
                    if (d1 < best[s]) { bsec[s] = best[s]; best[s] = d1; bidx[s] = code + 1; }
                    else if (d1 < bsec[s]) bsec[s] = d1;
                }
            }

        __syncthreads();   // all warps done reading buf[c&1]
        if (c + 2 < CHUNKS)
            fill_async(sb + OFF_B + (c & 1) * BUFSZ, c + 2, tid);
    }

    // quad reduce with top-2 merge, tie -> lowest index
    #pragma unroll
    for (int s = 0; s < 4; ++s) {
        float v = best[s], v2 = bsec[s]; int ix = bidx[s];
        #pragma unroll
        for (int off = 2; off > 0; off >>= 1) {
            float o1 = __shfl_down_sync(0xffffffffu, v, off, 4);
            int   oi = __shfl_down_sync(0xffffffffu, ix, off, 4);
            float o2 = __shfl_down_sync(0xffffffffu, v2, off, 4);
            if (o1 < v || (o1 == v && oi < ix)) { v2 = fminf(v, o2); v = o1; ix = oi; }
            else { v2 = fminf(v2, o1); }
        }
        best[s] = v; bsec[s] = v2; bidx[s] = ix;
    }
    if (wn == 0 && (lane & 3) == 0) {
        #pragma unroll
        for (int s = 0; s < 4; ++s) {
            bestA[rowid[s]] = best[s]; idxA[rowid[s]] = bidx[s]; b2A[rowid[s]] = bsec[s];
        }
    }
    __syncthreads();
    if (wn == 1 && (lane & 3) == 0) {
        #pragma unroll
        for (int s = 0; s < 4; ++s) {
            float a1 = bestA[rowid[s]], a2 = b2A[rowid[s]]; int ai = idxA[rowid[s]];
            float c1 = best[s], c2 = bsec[s]; int ci = bidx[s];
            float nb1, nb2; int ni1;
            if (c1 < a1 || (c1 == a1 && ci < ai)) { nb1 = c1; ni1 = ci; nb2 = fminf(a1, c2); }
            else { nb1 = a1; ni1 = ai; nb2 = fminf(a2, c1); }
            int row = rbase + rowid[s];
            g_idx[row] = ni1;
            float margin = __fmaf_rn(nb1, 3e-7f, 2e-7f);
            if (!(nb2 - nb1 > margin)) {
                int pos = atomicAdd(&g_cnt, 1);
                g_list[pos] = row;
            }
        }
    }
}

// ---- stage 2: exact sequential-fp32 recompute for flagged rows ----
__global__ __launch_bounds__(256)
void k_exact(const float* __restrict__ z, const float* __restrict__ emb) {
    __shared__ float zrow[16][DIM];
    __shared__ float es[DIM * 65];
    const int tid = threadIdx.x;
    const int cnt = g_cnt;
    const int rsub = tid >> 4, clane = tid & 15;

    for (int base = blockIdx.x * 16; base < cnt; base += gridDim.x * 16) {
        const int nrows = min(16, cnt - base);
        __syncthreads();
        for (int i = tid; i < nrows * 32; i += 256) {
            int rr = i >> 5, q = i & 31;
            int row = g_list[base + rr];
            ((float4*)zrow[rr])[q] = ((const float4*)(z + (size_t)row * DIM))[q];
        }
        __syncthreads();

        const bool active = rsub < nrows;
        float s = 0.f;
        if (active) {
            #pragma unroll 8
            for (int k = 0; k < DIM; ++k) {
                float v = zrow[rsub][k];
                s = __fadd_rn(s, __fmul_rn(v, v));
            }
        }
        float best = CUDART_INF_F; int bidx = 0;

        for (int ch = 0; ch < 32; ++ch) {
            __syncthreads();
            for (int i = tid; i < 64 * 32; i += 256) {
                int cl = i >> 5, q = i & 31;
                float4 v = ((const float4*)(emb + (size_t)(ch * 64 + cl) * DIM))[q];
                es[(q * 4 + 0) * 65 + cl] = v.x;
                es[(q * 4 + 1) * 65 + cl] = v.y;
                es[(q * 4 + 2) * 65 + cl] = v.z;
                es[(q * 4 + 3) * 65 + cl] = v.w;
            }
            __syncthreads();
            if (active) {
                #pragma unroll
                for (int j = 0; j < 4; ++j) {
                    int c = clane + 16 * j;
                    float m = 0.f;
                    #pragma unroll 8
                    for (int k = 0; k < DIM; ++k)
                        m = __fmaf_rn(zrow[rsub][k], es[k * 65 + c], m);
                    float d = __fadd_rn(__fsub_rn(s, __fmul_rn(2.f, m)), g_t[ch * 64 + c]);
                    int code = ch * 64 + c;
                    if (d < best) { best = d; bidx = code; }
                }
            }
        }
        #pragma unroll
        for (int off = 8; off > 0; off >>= 1) {
            float v2 = __shfl_down_sync(0xffffffffu, best, off, 16);
            int   i2 = __shfl_down_sync(0xffffffffu, bidx, off, 16);
            if (v2 < best || (v2 == best && i2 < bidx)) { best = v2; bidx = i2; }
        }
        if (active && clane == 0)
            g_idx[g_list[base + rsub]] = bidx;
    }
}

// ---- gather + straight-through + indices + loss partials ----
__global__ __launch_bounds__(256)
void k_out(const float* __restrict__ z, const float* __restrict__ emb,
           float* __restrict__ out, long long out_size) {
    __shared__ float red[256];
    const int tid = threadIdx.x;
    const long long row0 = (long long)blockIdx.x * 64;
    float lsum = 0.f;

    for (int i = tid; i < 64 * (DIM / 4); i += 256) {
        long long r  = row0 + (i >> 5);
        int       d4 = (i & 31) * 4;
        int idx = g_idx[r];
        float4 q  = *(const float4*)(emb + (size_t)idx * DIM + d4);
        long long gi = r * DIM + d4;
        float4 zz = *(const float4*)(z + gi);
        float4 o; float df;
        df = __fsub_rn(q.x, zz.x); o.x = __fadd_rn(zz.x, df); lsum += df * df;
        df = __fsub_rn(q.y, zz.y); o.y = __fadd_rn(zz.y, df); lsum += df * df;
        df = __fsub_rn(q.z, zz.z); o.z = __fadd_rn(zz.z, df); lsum += df * df;
        df = __fsub_rn(q.w, zz.w); o.w = __fadd_rn(zz.w, df); lsum += df * df;
        if (gi + 3 < out_size) *(float4*)(out + gi) = o;
    }

    if (tid < 64) {
        long long r  = row0 + tid;
        long long gi = (long long)NZ + r;
        if (gi < out_size) out[gi] = (float)g_idx[r];
    }

    red[tid] = lsum;
    __syncthreads();
    for (int s = 128; s > 0; s >>= 1) {
        if (tid < s) red[tid] += red[tid + s];
        __syncthreads();
    }
    if (tid == 0) g_part[blockIdx.x] = red[0];
}

// ---- deterministic final loss reduce ----
__global__ void k_final(float* __restrict__ out, long long out_size) {
    __shared__ float red[256];
    const int tid = threadIdx.x;
    float s = 0.f;
    for (int i = tid; i < 1024; i += 256) s += g_part[i];
    red[tid] = s;
    __syncthreads();
    for (int w = 128; w > 0; w >>= 1) {
        if (tid < w) red[tid] += red[tid + w];
        __syncthreads();
    }
    if (tid == 0) {
        float m = red[0] / (float)NZ;
        float loss = __fadd_rn(m, __fmul_rn(0.25f, m));
        long long li = (long long)NZ + NROWS;
        if (li < out_size) out[li] = loss;
    }
}

extern "C" void kernel_launch(void* const* d_in, const int* in_sizes, int n_in,
                              void* d_out, int out_size) {
    const float* z   = (const float*)d_in[0];
    const float* emb = (const float*)d_in[1];
    float* out = (float*)d_out;

    cudaFuncSetAttribute(k_argmin_tc, cudaFuncAttributeMaxDynamicSharedMemorySize, SMEM_SZ);

    k_zero<<<1, 32>>>();
    k_embnorm<<<(KCODES + 255) / 256, 256>>>(emb);
    k_split<<<(KCODES * DIM) / 256, 256>>>(emb);
    k_argmin_tc<<<NROWS / TILE_M, NTH, SMEM_SZ>>>(z);
    k_exact<<<256, 256>>>(z, emb);
    k_out<<<NROWS / 64, 256>>>(z, emb, out, (long long)out_size);
    k_final<<<1, 256>>>(out, (long long)out_size);
}

// round 11
// speedup vs baseline: 2.9350x; 1.2843x over previous
#include <cuda_runtime.h>
#include <cuda_fp16.h>
#include <math_constants.h>
#include <cstdint>

#define DIM 128
#define KCODES 2048
#define NROWS 65536
#define NZ (NROWS * DIM)
#define TILE_M 128
#define CHUNK 64
#define CHUNKS 32
#define NTH 256

__device__ __align__(16) float g_t[KCODES];
__device__ int   g_idx[NROWS];
__device__ float g_part[1024];
__device__ __align__(16) __half g_bh[KCODES * DIM];   // g1' = fl16(2048*e)
__device__ int g_cnt;
__device__ int g_list[NROWS];

// ---- smem byte offsets (stage 1): ~106 KB -> 2 CTAs/SM ----
#define OFF_A    0          // 128 rows x 256B (h1) = 32768
#define OFF_B    32768      // 4 buffers x (64 codes x 256B) = 65536
#define BUFSZ    16384
#define OFF_TALL 98304      // 2048 f32
#define OFF_SROW 106496
#define OFF_BEST 107008
#define OFF_IDX  107520
#define OFF_B2   108032
#define SMEM_SZ  108544

// ---- PTX helpers ----
static __device__ __forceinline__ void ldsm4(uint32_t* r, uint32_t a) {
    asm volatile("ldmatrix.sync.aligned.m8n8.x4.shared.b16 {%0,%1,%2,%3}, [%4];"
                 : "=r"(r[0]), "=r"(r[1]), "=r"(r[2]), "=r"(r[3]) : "r"(a));
}
static __device__ __forceinline__ void mma16816(float* c, const uint32_t* a,
                                                uint32_t b0, uint32_t b1) {
    asm volatile("mma.sync.aligned.m16n8k16.row.col.f32.f16.f16.f32 "
                 "{%0,%1,%2,%3}, {%4,%5,%6,%7}, {%8,%9}, {%0,%1,%2,%3};"
                 : "+f"(c[0]), "+f"(c[1]), "+f"(c[2]), "+f"(c[3])
                 : "r"(a[0]), "r"(a[1]), "r"(a[2]), "r"(a[3]), "r"(b0), "r"(b1));
}
#define CP_ASYNC16(d, s) asm volatile("cp.async.ca.shared.global [%0], [%1], 16;" :: "r"(d), "l"(s))
#define CP_COMMIT() asm volatile("cp.async.commit_group;" ::: "memory")
#define CP_WAIT0()  asm volatile("cp.async.wait_group 0;" ::: "memory")
#define CP_WAIT1()  asm volatile("cp.async.wait_group 1;" ::: "memory")
#define CP_WAIT2()  asm volatile("cp.async.wait_group 2;" ::: "memory")

// ---- prep: ||e||^2, exact sequential fp32, coalesced via smem staging ----
// grid 16 x 128 threads; block handles 128 codes; also zeroes g_cnt.
__global__ __launch_bounds__(128)
void k_embnorm(const float* __restrict__ emb) {
    __shared__ float sm[128 * 33];
    const int tid = threadIdx.x;
    const int cb = blockIdx.x * 128;
    if (blockIdx.x == 0 && tid == 0) g_cnt = 0;
    float s = 0.f;
    for (int kc = 0; kc < 4; ++kc) {
        __syncthreads();
        for (int i = tid; i < 128 * 32; i += 128) {
            int cl = i >> 5, kk = i & 31;
            sm[cl * 33 + kk] = emb[(size_t)(cb + cl) * DIM + kc * 32 + kk];
        }
        __syncthreads();
        // sequential order preserved: k ascending
        #pragma unroll 8
        for (int kk = 0; kk < 32; ++kk) {
            float v = sm[tid * 33 + kk];
            s = __fadd_rn(s, __fmul_rn(v, v));
        }
    }
    g_t[cb + tid] = s;
}

// ---- prep: f16 codebook, scaled by 2048 (exact power of 2) ----
__global__ void k_split(const float* __restrict__ emb) {
    int idx = blockIdx.x * blockDim.x + threadIdx.x;   // KCODES*DIM threads
    g_bh[idx] = __float2half_rn(__fmul_rn(emb[idx], 2048.0f));
}

// ---- B-chunk async fill: 64 codes x 16 16B-units, XOR-swizzled ----
static __device__ __forceinline__ void fill_async(uint32_t bBase, int chunk, int tid) {
    const char* src = (const char*)g_bh + (size_t)chunk * CHUNK * 256;
    #pragma unroll
    for (int j = 0; j < 4; ++j) {
        int i = tid + j * NTH;             // < 1024
        int code = i >> 4;
        int kg = i & 15;
        uint32_t d = bBase + (uint32_t)(code * 256 + (((kg & ~7) | ((kg ^ code) & 7)) << 4));
        CP_ASYNC16(d, src + code * 256 + kg * 16);
    }
    CP_COMMIT();
}

// ---- stage 1: pure-f16 HMMA distance GEMM (K=128) + argmin + top-2 margin flag ----
// 2 CTAs/SM, 8 warps = 4m x 2n, warp tile 32 rows x 32 codes, chunk 64 codes.
__global__ __launch_bounds__(NTH, 2)
void k_argmin_tc(const float* __restrict__ z) {
    extern __shared__ char smc[];
    uint32_t sb;
    asm("{ .reg .u64 t; cvta.to.shared.u64 t, %1; cvt.u32.u64 %0, t; }" : "=r"(sb) : "l"(smc));
    float* tall  = (float*)(smc + OFF_TALL);
    float* srow  = (float*)(smc + OFF_SROW);
    float* bestA = (float*)(smc + OFF_BEST);
    int*   idxA  = (int*)(smc + OFF_IDX);
    float* b2A   = (float*)(smc + OFF_B2);

    const int tid = threadIdx.x;
    const int lane = tid & 31, wid = tid >> 5;
    const int wm = wid & 3, wn = wid >> 2;
    const int rbase = blockIdx.x * TILE_M;

    // prologue: 3 chunk fills in flight
    fill_async(sb + OFF_B + 0 * BUFSZ, 0, tid);
    fill_async(sb + OFF_B + 1 * BUFSZ, 1, tid);
    fill_async(sb + OFF_B + 2 * BUFSZ, 2, tid);

    for (int i = tid; i < KCODES / 4; i += NTH)
        ((float4*)tall)[i] = ((const float4*)g_t)[i];

    // build A tile (h1 = fl16(z)), 256B/row, XOR-swizzled
    {
        int r = tid >> 1, half = tid & 1;
        const float* zr = z + (size_t)(rbase + r) * DIM + half * 64;
        char* arow = smc + OFF_A + r * 256;
        int rx = r & 7;
        #pragma unroll
        for (int g = 0; g < 8; ++g) {
            float4 v0 = *(const float4*)(zr + g * 8);
            float4 v1 = *(const float4*)(zr + g * 8 + 4);
            float f[8] = {v0.x, v0.y, v0.z, v0.w, v1.x, v1.y, v1.z, v1.w};
            uint32_t hp[4];
            #pragma unroll
            for (int e = 0; e < 4; ++e) {
                __half a = __float2half_rn(f[2 * e]);
                __half b = __float2half_rn(f[2 * e + 1]);
                hp[e] = (uint32_t)__half_as_ushort(a) | ((uint32_t)__half_as_ushort(b) << 16);
            }
            int kg0 = half * 8 + g;
            int ks0 = (kg0 & ~7) | ((kg0 & 7) ^ rx);
            *(uint4*)(arow + ks0 * 16) = *(uint4*)hp;
        }
    }

    if (tid < TILE_M) {
        const float* zr = z + (size_t)(rbase + tid) * DIM;
        float s = 0.f;
        #pragma unroll 8
        for (int k = 0; k < DIM; ++k)
            s = __fadd_rn(s, __fmul_rn(zr[k], zr[k]));
        srow[tid] = s;
    }
    __syncthreads();

    const int rx7 = lane & 7;
    const int klane = (lane >> 4) & 1;
    const uint32_t aRow0 = sb + OFF_A +
        (uint32_t)((wm * 32 + (lane & 7) + ((lane & 8) ? 8 : 0)) * 256);
    const uint32_t bRowOff =
        (uint32_t)((wn * 32 + (lane & 7) + ((lane & 8) ? 8 : 0)) * 256);

    float s_r[4]; int rowid[4];
    #pragma unroll
    for (int mi = 0; mi < 2; ++mi)
        #pragma unroll
        for (int h = 0; h < 2; ++h) {
            int rr = wm * 32 + mi * 16 + (lane >> 2) + 8 * h;
            rowid[mi * 2 + h] = rr;
            s_r[mi * 2 + h] = srow[rr];
        }
    float best[4], bsec[4]; int bidx[4];
    #pragma unroll
    for (int s = 0; s < 4; ++s) { best[s] = CUDART_INF_F; bsec[s] = CUDART_INF_F; bidx[s] = 0; }

    for (int c = 0; c < CHUNKS; ++c) {
        if (c < CHUNKS - 2) CP_WAIT2(); else if (c == CHUNKS - 2) CP_WAIT1(); else CP_WAIT0();
        __syncthreads();   // fill(c) visible; all warps done with buf[(c-1)&3]
        if (c + 3 < CHUNKS)
            fill_async(sb + OFF_B + ((c + 3) & 3) * BUFSZ, c + 3, tid);
        const uint32_t bBase = sb + OFF_B + (c & 3) * BUFSZ;

        float acc[2][4][4];
        #pragma unroll
        for (int i = 0; i < 32; ++i) ((float*)acc)[i] = 0.f;

        // K=128: 8 k16 steps; per step 4 ldsm.x4 + 8 mma
        #pragma unroll
        for (int ks = 0; ks < 8; ++ks) {
            const int C = ks * 2 + klane;   // 16B unit 0..15
            const uint32_t slot = (uint32_t)(((C & ~7) | ((C & 7) ^ rx7)) << 4);
            uint32_t A0[4], A1[4], B0[4], B1[4];
            ldsm4(A0, aRow0 + slot);
            ldsm4(A1, aRow0 + 16 * 256 + slot);
            ldsm4(B0, bBase + bRowOff + slot);
            ldsm4(B1, bBase + bRowOff + 16 * 256 + slot);
            mma16816(acc[0][0], A0, B0[0], B0[2]);
            mma16816(acc[0][1], A0, B0[1], B0[3]);
            mma16816(acc[0][2], A0, B1[0], B1[2]);
            mma16816(acc[0][3], A0, B1[1], B1[3]);
            mma16816(acc[1][0], A1, B0[0], B0[2]);
            mma16816(acc[1][1], A1, B0[1], B0[3]);
            mma16816(acc[1][2], A1, B1[0], B1[2]);
            mma16816(acc[1][3], A1, B1[1], B1[3]);
        }

        // epilogue: d = fl(fl(s - acc*2^-10) + t); ascending codes; strict <
        const int cb0 = c * CHUNK + wn * 32 + 2 * (lane & 3);
        #pragma unroll
        for (int mi = 0; mi < 2; ++mi)
            #pragma unroll
            for (int ni = 0; ni < 4; ++ni) {
                const float* cc = acc[mi][ni];
                int code = cb0 + ni * 8;
                float t0 = tall[code], t1 = tall[code + 1];
                #pragma unroll
                for (int h = 0; h < 2; ++h) {
                    int s = mi * 2 + h;
                    float d0 = __fadd_rn(__fsub_rn(s_r[s], __fmul_rn(cc[2 * h],     9.765625e-4f)), t0);
                    float d1 = __fadd_rn(__fsub_rn(s_r[s], __fmul_rn(cc[2 * h + 1], 9.765625e-4f)), t1);
                    if (d0 < best[s]) { bsec[s] = best[s]; best[s] = d0; bidx[s] = code; }
                    else if (d0 < bsec[s]) bsec[s] = d0;
                    if (d1 < best[s]) { bsec[s] = best[s]; best[s] = d1; bidx[s] = code + 1; }
                    else if (d1 < bsec[s]) bsec[s] = d1;
                }
            }
    }

    // quad reduce with top-2 merge, tie -> lowest index
    #pragma unroll
    for (int s = 0; s < 4; ++s) {
        float v = best[s], v2 = bsec[s]; int ix = bidx[s];
        #pragma unroll
        for (int off = 2; off > 0; off >>= 1) {
            float o1 = __shfl_down_sync(0xffffffffu, v, off, 4);
            int   oi = __shfl_down_sync(0xffffffffu, ix, off, 4);
            float o2 = __shfl_down_sync(0xffffffffu, v2, off, 4);
            if (o1 < v || (o1 == v && oi < ix)) { v2 = fminf(v, o2); v = o1; ix = oi; }
            else { v2 = fminf(v2, o1); }
        }
        best[s] = v; bsec[s] = v2; bidx[s] = ix;
    }
    if (wn == 0 && (lane & 3) == 0) {
        #pragma unroll
        for (int s = 0; s < 4; ++s) {
            bestA[rowid[s]] = best[s]; idxA[rowid[s]] = bidx[s]; b2A[rowid[s]] = bsec[s];
        }
    }
    __syncthreads();
    if (wn == 1 && (lane & 3) == 0) {
        #pragma unroll
        for (int s = 0; s < 4; ++s) {
            float a1 = bestA[rowid[s]], a2 = b2A[rowid[s]]; int ai = idxA[rowid[s]];
            float c1 = best[s], c2 = bsec[s]; int ci = bidx[s];
            float nb1, nb2; int ni1;
            if (c1 < a1 || (c1 == a1 && ci < ai)) { nb1 = c1; ni1 = ci; nb2 = fminf(a1, c2); }
            else { nb1 = a1; ni1 = ai; nb2 = fminf(a2, c1); }
            int row = rbase + rowid[s];
            g_idx[row] = ni1;
            // flag gap < 2.5ulp(d) + 3e-5 (covers f16 GEMM error tail) for exact recompute
            float margin = __fmaf_rn(nb1, 3e-7f, 3e-5f);
            if (!(nb2 - nb1 > margin)) {
                int pos = atomicAdd(&g_cnt, 1);
                g_list[pos] = row;
            }
        }
    }
}

// ---- stage 2: exact sequential-fp32 recompute for flagged rows ----
__global__ __launch_bounds__(256)
void k_exact(const float* __restrict__ z, const float* __restrict__ emb) {
    __shared__ float zrow[16][DIM];
    __shared__ float es[DIM * 65];
    const int tid = threadIdx.x;
    const int cnt = g_cnt;
    const int rsub = tid >> 4, clane = tid & 15;

    for (int base = blockIdx.x * 16; base < cnt; base += gridDim.x * 16) {
        const int nrows = min(16, cnt - base);
        __syncthreads();
        for (int i = tid; i < nrows * 32; i += 256) {
            int rr = i >> 5, q = i & 31;
            int row = g_list[base + rr];
            ((float4*)zrow[rr])[q] = ((const float4*)(z + (size_t)row * DIM))[q];
        }
        __syncthreads();

        const bool active = rsub < nrows;
        float s = 0.f;
        if (active) {
            #pragma unroll 8
            for (int k = 0; k < DIM; ++k) {
                float v = zrow[rsub][k];
                s = __fadd_rn(s, __fmul_rn(v, v));
            }
        }
        float best = CUDART_INF_F; int bidx = 0;

        for (int ch = 0; ch < 32; ++ch) {
            __syncthreads();
            for (int i = tid; i < 64 * 32; i += 256) {
                int cl = i >> 5, q = i & 31;
                float4 v = ((const float4*)(emb + (size_t)(ch * 64 + cl) * DIM))[q];
                es[(q * 4 + 0) * 65 + cl] = v.x;
                es[(q * 4 + 1) * 65 + cl] = v.y;
                es[(q * 4 + 2) * 65 + cl] = v.z;
                es[(q * 4 + 3) * 65 + cl] = v.w;
            }
            __syncthreads();
            if (active) {
                #pragma unroll
                for (int j = 0; j < 4; ++j) {
                    int c = clane + 16 * j;
                    float m = 0.f;
                    #pragma unroll 8
                    for (int k = 0; k < DIM; ++k)
                        m = __fmaf_rn(zrow[rsub][k], es[k * 65 + c], m);
                    float d = __fadd_rn(__fsub_rn(s, __fmul_rn(2.f, m)), g_t[ch * 64 + c]);
                    int code = ch * 64 + c;
                    if (d < best) { best = d; bidx = code; }
                }
            }
        }
        #pragma unroll
        for (int off = 8; off > 0; off >>= 1) {
            float v2 = __shfl_down_sync(0xffffffffu, best, off, 16);
            int   i2 = __shfl_down_sync(0xffffffffu, bidx, off, 16);
            if (v2 < best || (v2 == best && i2 < bidx)) { best = v2; bidx = i2; }
        }
        if (active && clane == 0)
            g_idx[g_list[base + rsub]] = bidx;
    }
}

// ---- gather + straight-through + indices + loss partials ----
__global__ __launch_bounds__(256)
void k_out(const float* __restrict__ z, const float* __restrict__ emb,
           float* __restrict__ out, long long out_size) {
    __shared__ float red[256];
    const int tid = threadIdx.x;
    const long long row0 = (long long)blockIdx.x * 64;
    float lsum = 0.f;

    for (int i = tid; i < 64 * (DIM / 4); i += 256) {
        long long r  = row0 + (i >> 5);
        int       d4 = (i & 31) * 4;
        int idx = g_idx[r];
        float4 q  = *(const float4*)(emb + (size_t)idx * DIM + d4);
        long long gi = r * DIM + d4;
        float4 zz = *(const float4*)(z + gi);
        float4 o; float df;
        df = __fsub_rn(q.x, zz.x); o.x = __fadd_rn(zz.x, df); lsum += df * df;
        df = __fsub_rn(q.y, zz.y); o.y = __fadd_rn(zz.y, df); lsum += df * df;
        df = __fsub_rn(q.z, zz.z); o.z = __fadd_rn(zz.z, df); lsum += df * df;
        df = __fsub_rn(q.w, zz.w); o.w = __fadd_rn(zz.w, df); lsum += df * df;
        if (gi + 3 < out_size) *(float4*)(out + gi) = o;
    }

    if (tid < 64) {
        long long r  = row0 + tid;
        long long gi = (long long)NZ + r;
        if (gi < out_size) out[gi] = (float)g_idx[r];
    }

    red[tid] = lsum;
    __syncthreads();
    for (int s = 128; s > 0; s >>= 1) {
        if (tid < s) red[tid] += red[tid + s];
        __syncthreads();
    }
    if (tid == 0) g_part[blockIdx.x] = red[0];
}

// ---- deterministic final loss reduce ----
__global__ void k_final(float* __restrict__ out, long long out_size) {
    __shared__ float red[256];
    const int tid = threadIdx.x;
    float s = 0.f;
    for (int i = tid; i < 1024; i += 256) s += g_part[i];
    red[tid] = s;
    __syncthreads();
    for (int w = 128; w > 0; w >>= 1) {
        if (tid < w) red[tid] += red[tid + w];
        __syncthreads();
    }
    if (tid == 0) {
        float m = red[0] / (float)NZ;
        float loss = __fadd_rn(m, __fmul_rn(0.25f, m));
        long long li = (long long)NZ + NROWS;
        if (li < out_size) out[li] = loss;
    }
}

extern "C" void kernel_launch(void* const* d_in, const int* in_sizes, int n_in,
                              void* d_out, int out_size) {
    const float* z   = (const float*)d_in[0];
    const float* emb = (const float*)d_in[1];
    float* out = (float*)d_out;

    cudaFuncSetAttribute(k_argmin_tc, cudaFuncAttributeMaxDynamicSharedMemorySize, SMEM_SZ);

    k_embnorm<<<16, 128>>>(emb);
    k_split<<<(KCODES * DIM) / 256, 256>>>(emb);
    k_argmin_tc<<<NROWS / TILE_M, NTH, SMEM_SZ>>>(z);
    k_exact<<<512, 256>>>(z, emb);
    k_out<<<NROWS / 64, 256>>>(z, emb, out, (long long)out_size);
    k_final<<<1, 256>>>(out, (long long)out_size);
}